// round 10
// baseline (speedup 1.0000x reference)
#include <cuda_runtime.h>
#include <math_constants.h>

// ---------------- configuration ---------------------------------------------
#define KEY_LO 0x42FFFFFFu   // fkey(-0.03125f)
#define KEY_HI 0xBD000000u   // fkey(+0.03125f)
#define MAXN   33554432
#define NB_A   4096
#define NB_B   1024

// ---------------- device state (allocation-free, self-restoring) -------------
__device__ __align__(16) unsigned g_scratch[MAXN];
__device__ unsigned g_hA[NB_A];
__device__ unsigned g_hB[NB_B];
__device__ unsigned g_hC[NB_B];
__device__ unsigned g_below, g_m, g_use_fallback, g_rank;
__device__ unsigned g_b1, g_k2, g_b2, g_k3;
__device__ unsigned g_tk[4];          // per-kernel completion tickets
__device__ float    g_median;

// monotonic key: order-preserving float -> uint
__device__ __forceinline__ unsigned fkey(float f) {
    unsigned b = __float_as_uint(f);
    unsigned mask = (unsigned)((int)b >> 31) | 0x80000000u;
    return b ^ mask;
}

// ---------------- pass 1: below-count + compaction + fused decide ------------
__global__ __launch_bounds__(512) void pass1_kernel(const float4* __restrict__ x,
                                                    int n4, int n, unsigned k) {
    __shared__ unsigned s_last;
    int tid = threadIdx.x, lane = tid & 31;
    int chunk = (n4 + gridDim.x - 1) / gridDim.x;
    int base = blockIdx.x * chunk;
    int end = base + chunk;
    if (end > n4) end = n4;

    unsigned below = 0;
    const float4 FILL = make_float4(CUDART_INF_F, CUDART_INF_F, CUDART_INF_F, CUDART_INF_F);
    const unsigned lanemask = (1u << lane) - 1u;

    // warp-uniform loop bound: i0 identical across the warp -> ballots are safe
    for (int i0 = base + (tid & ~31); i0 < end; i0 += 1024) {
        int ia = i0 + lane;
        int ib = i0 + 512 + lane;
        float4 v0 = (ia < end) ? x[ia] : FILL;
        float4 v1 = (ib < end) ? x[ib] : FILL;

        unsigned kk[8];
        kk[0] = fkey(v0.x); kk[1] = fkey(v0.y); kk[2] = fkey(v0.z); kk[3] = fkey(v0.w);
        kk[4] = fkey(v1.x); kk[5] = fkey(v1.y); kk[6] = fkey(v1.z); kk[7] = fkey(v1.w);

        unsigned msk[8], tot = 0;
        #pragma unroll
        for (int j = 0; j < 8; j++) {
            below += (kk[j] < KEY_LO) ? 1u : 0u;
            bool w = (kk[j] - KEY_LO) < (KEY_HI - KEY_LO);
            msk[j] = __ballot_sync(0xffffffffu, w);
            tot += __popc(msk[j]);
        }
        if (tot) {
            unsigned gb = 0;
            if (lane == 0) gb = atomicAdd(&g_m, tot);
            gb = __shfl_sync(0xffffffffu, gb, 0);
            #pragma unroll
            for (int j = 0; j < 8; j++) {
                if (msk[j] & (1u << lane))
                    g_scratch[gb + __popc(msk[j] & lanemask)] = kk[j];
                gb += __popc(msk[j]);
            }
        }
    }

    // scalar tail (n not multiple of 4)
    if (blockIdx.x == 0 && tid == 0) {
        const float* xf = (const float*)x;
        for (int j = n4 * 4; j < n; j++) {
            unsigned key = fkey(xf[j]);
            if (key < KEY_LO) below++;
            else if ((key - KEY_LO) < (KEY_HI - KEY_LO))
                g_scratch[atomicAdd(&g_m, 1u)] = key;
        }
    }

    #pragma unroll
    for (int o = 16; o; o >>= 1) below += __shfl_down_sync(0xffffffffu, below, o);
    if (lane == 0 && below) atomicAdd(&g_below, below);

    // last block decides speculation hit vs fallback
    __threadfence();
    if (tid == 0) s_last = (atomicAdd(&g_tk[0], 1u) == gridDim.x - 1u) ? 1u : 0u;
    __syncthreads();
    if (s_last && tid == 0) {
        __threadfence();
        unsigned b = g_below, m = g_m;
        bool hit = (k >= b) && ((k - b) < m);
        g_use_fallback = hit ? 0u : 1u;
        g_rank = hit ? (k - b) : k;
        if (!hit) g_m = (unsigned)n;
        g_tk[0] = 0;
    }
}

// ---------------- fallback: exact full compaction (gated) --------------------
__global__ __launch_bounds__(512) void fallback_kernel(const float4* __restrict__ x,
                                                       int n4, int n) {
    if (g_use_fallback == 0u) return;
    int stride = gridDim.x * blockDim.x;
    uint4* s4 = (uint4*)g_scratch;
    for (int i = blockIdx.x * blockDim.x + threadIdx.x; i < n4; i += stride) {
        float4 v = x[i];
        s4[i] = make_uint4(fkey(v.x), fkey(v.y), fkey(v.z), fkey(v.w));
    }
    if (blockIdx.x == 0 && threadIdx.x == 0) {
        const float* xf = (const float*)x;
        for (int j = n4 * 4; j < n; j++) g_scratch[j] = fkey(xf[j]);
    }
}

// ---------------- histA (top 12 bits) + fused select + self-zero -------------
__global__ __launch_bounds__(256) void histA_kernel() {
    __shared__ unsigned sh[NB_A];
    __shared__ unsigned ps[256];
    __shared__ unsigned s_last;
    int tid = threadIdx.x;
    for (int i = tid; i < NB_A; i += 256) sh[i] = 0;
    __syncthreads();
    unsigned m = g_m, stride = gridDim.x * 256;
    for (unsigned i = blockIdx.x * 256 + tid; i < m; i += stride)
        atomicAdd(&sh[g_scratch[i] >> 20], 1u);
    __syncthreads();
    for (int i = tid; i < NB_A; i += 256)
        if (sh[i]) atomicAdd(&g_hA[i], sh[i]);

    __threadfence();
    if (tid == 0) s_last = (atomicAdd(&g_tk[1], 1u) == gridDim.x - 1u) ? 1u : 0u;
    __syncthreads();
    if (!s_last) return;
    __threadfence();

    // select bin containing g_rank (256 threads x 16 bins)
    unsigned c[16], s = 0;
    #pragma unroll
    for (int j = 0; j < 16; j++) { c[j] = g_hA[tid * 16 + j]; s += c[j]; }
    ps[tid] = s;
    __syncthreads();
    for (int off = 1; off < 256; off <<= 1) {
        unsigned v = (tid >= off) ? ps[tid - off] : 0u;
        __syncthreads();
        ps[tid] += v;
        __syncthreads();
    }
    unsigned k = g_rank, incl = ps[tid], excl = incl - s;
    if (k >= excl && k < incl) {
        unsigned r = k - excl;
        #pragma unroll
        for (int j = 0; j < 16; j++) {
            if (r < c[j]) { g_b1 = tid * 16 + j; g_k2 = r; break; }
            r -= c[j];
        }
    }
    #pragma unroll
    for (int j = 0; j < 16; j++) g_hA[tid * 16 + j] = 0;
    if (tid == 0) g_tk[1] = 0;
}

// ---------------- histB (bits 10..19) + fused select + self-zero -------------
__global__ __launch_bounds__(256) void histB_kernel() {
    __shared__ unsigned sh[NB_B];
    __shared__ unsigned ps[256];
    __shared__ unsigned s_last;
    int tid = threadIdx.x;
    for (int i = tid; i < NB_B; i += 256) sh[i] = 0;
    __syncthreads();
    unsigned b1 = g_b1, m = g_m, stride = gridDim.x * 256;
    for (unsigned i = blockIdx.x * 256 + tid; i < m; i += stride) {
        unsigned u = g_scratch[i];
        if ((u >> 20) == b1) atomicAdd(&sh[(u >> 10) & 1023u], 1u);
    }
    __syncthreads();
    for (int i = tid; i < NB_B; i += 256)
        if (sh[i]) atomicAdd(&g_hB[i], sh[i]);

    __threadfence();
    if (tid == 0) s_last = (atomicAdd(&g_tk[2], 1u) == gridDim.x - 1u) ? 1u : 0u;
    __syncthreads();
    if (!s_last) return;
    __threadfence();

    unsigned c[4], s = 0;
    #pragma unroll
    for (int j = 0; j < 4; j++) { c[j] = g_hB[tid * 4 + j]; s += c[j]; }
    ps[tid] = s;
    __syncthreads();
    for (int off = 1; off < 256; off <<= 1) {
        unsigned v = (tid >= off) ? ps[tid - off] : 0u;
        __syncthreads();
        ps[tid] += v;
        __syncthreads();
    }
    unsigned k = g_k2, incl = ps[tid], excl = incl - s;
    if (k >= excl && k < incl) {
        unsigned r = k - excl;
        #pragma unroll
        for (int j = 0; j < 4; j++) {
            if (r < c[j]) { g_b2 = tid * 4 + j; g_k3 = r; break; }
            r -= c[j];
        }
    }
    #pragma unroll
    for (int j = 0; j < 4; j++) g_hB[tid * 4 + j] = 0;
    if (tid == 0) g_tk[2] = 0;
}

// ---------------- histC (low 10 bits) + median + global self-reset -----------
__global__ __launch_bounds__(256) void histC_kernel() {
    __shared__ unsigned sh[NB_B];
    __shared__ unsigned ps[256];
    __shared__ unsigned s_last;
    int tid = threadIdx.x;
    for (int i = tid; i < NB_B; i += 256) sh[i] = 0;
    __syncthreads();
    unsigned hi = (g_b1 << 10) | g_b2, m = g_m, stride = gridDim.x * 256;
    for (unsigned i = blockIdx.x * 256 + tid; i < m; i += stride) {
        unsigned u = g_scratch[i];
        if ((u >> 10) == hi) atomicAdd(&sh[u & 1023u], 1u);
    }
    __syncthreads();
    for (int i = tid; i < NB_B; i += 256)
        if (sh[i]) atomicAdd(&g_hC[i], sh[i]);

    __threadfence();
    if (tid == 0) s_last = (atomicAdd(&g_tk[3], 1u) == gridDim.x - 1u) ? 1u : 0u;
    __syncthreads();
    if (!s_last) return;
    __threadfence();

    unsigned c[4], s = 0;
    #pragma unroll
    for (int j = 0; j < 4; j++) { c[j] = g_hC[tid * 4 + j]; s += c[j]; }
    ps[tid] = s;
    __syncthreads();
    for (int off = 1; off < 256; off <<= 1) {
        unsigned v = (tid >= off) ? ps[tid - off] : 0u;
        __syncthreads();
        ps[tid] += v;
        __syncthreads();
    }
    unsigned k = g_k3, incl = ps[tid], excl = incl - s;
    if (k >= excl && k < incl) {
        unsigned r = k - excl;
        #pragma unroll
        for (int j = 0; j < 4; j++) {
            if (r < c[j]) {
                unsigned key  = (g_b1 << 20) | (g_b2 << 10) | (unsigned)(tid * 4 + j);
                unsigned bits = (key & 0x80000000u) ? (key ^ 0x80000000u) : ~key;
                g_median = __uint_as_float(bits);
                break;
            }
            r -= c[j];
        }
    }
    #pragma unroll
    for (int j = 0; j < 4; j++) g_hC[tid * 4 + j] = 0;
    if (tid == 0) { g_below = 0; g_m = 0; g_tk[3] = 0; }
}

// ---------------- fused threshold + 7x7 maxpool + NMS (vectorized) -----------
#define IMG_W  2048
#define IMG_H  2048
#define IMG_W4 512
#define TW  128
#define TH  32
#define SWP 136     // padded tile width in floats (34 float4: cols -4..131)
#define SHH 38      // 32 + 2*3 halo rows

__global__ __launch_bounds__(256) void nms_kernel(const float4* __restrict__ x4,
                                                  float4* __restrict__ o4) {
    __shared__ float sthr[SHH][SWP];
    __shared__ float shm[SHH][TW];
    const float med = g_median;
    int tid = threadIdx.x;
    int bx = blockIdx.x, by = blockIdx.y;
    const float4* img  = x4 + (size_t)blockIdx.z * IMG_W4 * IMG_H;
    float4*       oimg = o4 + (size_t)blockIdx.z * IMG_W4 * IMG_H;
    int gx4_0 = bx * (TW / 4) - 1;     // float4 col of padded col 0
    int gy0   = by * TH - 3;

    // load + threshold (all float4, aligned; OOB float4s are wholly OOB -> -inf)
    for (int idx = tid; idx < SHH * 34; idx += 256) {
        int r = idx / 34, q = idx - r * 34;
        int gy = gy0 + r, gx4 = gx4_0 + q;
        float4 v = make_float4(-CUDART_INF_F, -CUDART_INF_F, -CUDART_INF_F, -CUDART_INF_F);
        if (gy >= 0 && gy < IMG_H && gx4 >= 0 && gx4 < IMG_W4) {
            float4 t = img[(size_t)gy * IMG_W4 + gx4];
            v.x = (t.x > med) ? t.x : 0.0f;
            v.y = (t.y > med) ? t.y : 0.0f;
            v.z = (t.z > med) ? t.z : 0.0f;
            v.w = (t.w > med) ? t.w : 0.0f;
        }
        *(float4*)&sthr[r][q * 4] = v;
    }
    __syncthreads();

    // horizontal 7-max: 3x LDS.128 -> 4 outputs via shared max-tree
    for (int idx = tid; idx < SHH * 32; idx += 256) {
        int r = idx >> 5, t = idx & 31;
        float4 a = *(const float4*)&sthr[r][t * 4];
        float4 b = *(const float4*)&sthr[r][t * 4 + 4];
        float4 cc = *(const float4*)&sthr[r][t * 4 + 8];
        // padded cols 4t..4t+11 = a.xyzw b.xyzw cc.xyzw; output j needs v[j+1..j+7]
        float m45 = fmaxf(b.x, b.y), m67 = fmaxf(b.z, b.w);
        float m4567 = fmaxf(m45, m67);
        float m23 = fmaxf(a.z, a.w);
        float m89 = fmaxf(cc.x, cc.y);
        float m0 = fmaxf(fmaxf(a.y, m23), m4567);
        float m1 = fmaxf(fmaxf(m23, m4567), cc.x);
        float m2 = fmaxf(fmaxf(a.w, m4567), m89);
        float m3 = fmaxf(fmaxf(m4567, m89), cc.z);
        *(float4*)&shm[r][t * 4] = make_float4(m0, m1, m2, m3);
    }
    __syncthreads();

    // vertical 7-max + local-max compare + STG.128
    for (int idx = tid; idx < TH * 32; idx += 256) {
        int r = idx >> 5, t = idx & 31;
        float4 m = *(const float4*)&shm[r][t * 4];
        #pragma unroll
        for (int o = 1; o < 7; o++) {
            float4 w = *(const float4*)&shm[r + o][t * 4];
            m.x = fmaxf(m.x, w.x);
            m.y = fmaxf(m.y, w.y);
            m.z = fmaxf(m.z, w.z);
            m.w = fmaxf(m.w, w.w);
        }
        float4 cen = *(const float4*)&sthr[r + 3][t * 4 + 4];
        float4 outv;
        outv.x = (cen.x == m.x) ? cen.x : 0.0f;
        outv.y = (cen.y == m.y) ? cen.y : 0.0f;
        outv.z = (cen.z == m.z) ? cen.z : 0.0f;
        outv.w = (cen.w == m.w) ? cen.w : 0.0f;
        int gy = by * TH + r;
        oimg[(size_t)gy * IMG_W4 + bx * 32 + t] = outv;
    }
}

// ---------------- launch -----------------------------------------------------
extern "C" void kernel_launch(void* const* d_in, const int* in_sizes, int n_in,
                              void* d_out, int out_size) {
    const float* x = (const float*)d_in[0];
    float* out = (float*)d_out;
    int n = in_sizes[0];
    int n4 = n >> 2;
    unsigned k = (unsigned)((n - 1) / 2);

    int dev = 0, sms = 148;
    cudaGetDevice(&dev);
    cudaDeviceGetAttribute(&sms, cudaDevAttrMultiProcessorCount, dev);

    pass1_kernel<<<sms * 4, 512>>>((const float4*)x, n4, n, k);
    fallback_kernel<<<sms * 4, 512>>>((const float4*)x, n4, n);
    histA_kernel<<<256, 256>>>();
    histB_kernel<<<256, 256>>>();
    histC_kernel<<<256, 256>>>();
    nms_kernel<<<dim3(IMG_W / TW, IMG_H / TH, 8), 256>>>((const float4*)x, (float4*)out);
}

// round 11
// speedup vs baseline: 1.0591x; 1.0591x over previous
#include <cuda_runtime.h>
#include <math_constants.h>

// ---------------- configuration ---------------------------------------------
#define KEY_LO 0x42FFFFFFu   // fkey(-0.03125f)
#define KEY_HI 0xBD000000u   // fkey(+0.03125f)
#define GCAP   (1u << 22)    // 4M-key scratch (16 MB)
#define BCAP   8192          // per-block smem append buffer
#define NB_A   4096
#define NB_B   1024

// ---------------- device state (allocation-free, self-restoring) -------------
__device__ __align__(16) unsigned g_scratch[GCAP];
__device__ unsigned g_hA[NB_A];
__device__ unsigned g_hB[NB_B];
__device__ unsigned g_hC[NB_B];
__device__ unsigned g_below, g_m, g_overflow, g_use_fallback, g_rank;
__device__ unsigned g_b1, g_k2, g_b2, g_k3;
__device__ unsigned g_tk[4];
__device__ float    g_median;

// monotonic key: order-preserving float -> uint
__device__ __forceinline__ unsigned fkey(float f) {
    unsigned b = __float_as_uint(f);
    unsigned mask = (unsigned)((int)b >> 31) | 0x80000000u;
    return b ^ mask;
}

// ---------------- pass 1: below-count + windowed compaction + decide ---------
__global__ __launch_bounds__(512) void pass1_kernel(const float4* __restrict__ x,
                                                    int n4, int n, unsigned k) {
    __shared__ unsigned buf[BCAP];
    __shared__ unsigned s_cnt, s_base, s_last;
    int tid = threadIdx.x;
    if (tid == 0) s_cnt = 0;
    __syncthreads();

    unsigned below = 0;
    int stride = gridDim.x * blockDim.x;

    auto proc = [&](float f) {
        unsigned key = fkey(f);
        below += (key < KEY_LO) ? 1u : 0u;
        if ((key - KEY_LO) < (KEY_HI - KEY_LO)) {        // rare (~2.5%)
            unsigned p = atomicAdd(&s_cnt, 1u);
            if (p < BCAP) buf[p] = key;
            else g_overflow = 1u;
        }
    };

    for (int i = blockIdx.x * blockDim.x + tid; i < n4; i += 2 * stride) {
        float4 v0 = x[i];
        bool r1 = (i + stride) < n4;
        float4 v1 = r1 ? x[i + stride]
                       : make_float4(CUDART_INF_F, CUDART_INF_F, CUDART_INF_F, CUDART_INF_F);
        proc(v0.x); proc(v0.y); proc(v0.z); proc(v0.w);
        proc(v1.x); proc(v1.y); proc(v1.z); proc(v1.w);
    }

    // scalar tail (n not multiple of 4)
    if (blockIdx.x == 0 && tid == 0) {
        const float* xf = (const float*)x;
        for (int j = n4 * 4; j < n; j++) proc(xf[j]);
    }

    #pragma unroll
    for (int o = 16; o; o >>= 1) below += __shfl_down_sync(0xffffffffu, below, o);
    if ((tid & 31) == 0 && below) atomicAdd(&g_below, below);

    __syncthreads();
    if (tid == 0) {
        unsigned c = s_cnt;
        if (c > BCAP) { c = BCAP; g_overflow = 1u; }
        s_cnt = c;
        s_base = atomicAdd(&g_m, c);
    }
    __syncthreads();
    unsigned cnt = s_cnt, base = s_base;
    for (unsigned j = tid; j < cnt; j += 512) {
        if (base + j < GCAP) g_scratch[base + j] = buf[j];
        else g_overflow = 1u;
    }

    // last block decides speculation hit vs fallback
    __threadfence();
    if (tid == 0) s_last = (atomicAdd(&g_tk[0], 1u) == gridDim.x - 1u) ? 1u : 0u;
    __syncthreads();
    if (s_last && tid == 0) {
        __threadfence();
        unsigned b = g_below, m = g_m;
        bool hit = (g_overflow == 0u) && (k >= b) && ((k - b) < m) && (m <= GCAP);
        g_use_fallback = hit ? 0u : 1u;
        g_rank = hit ? (k - b) : k;
        g_tk[0] = 0;
    }
}

// ---------------- histA (top 12 bits) + fused select + self-zero -------------
__global__ __launch_bounds__(256) void histA_kernel(const float4* __restrict__ x,
                                                    int n4, int n) {
    __shared__ unsigned sh[NB_A];
    __shared__ unsigned ps[256];
    __shared__ unsigned s_last;
    int tid = threadIdx.x;
    for (int i = tid; i < NB_A; i += 256) sh[i] = 0;
    __syncthreads();

    unsigned stride = gridDim.x * 256;
    if (g_use_fallback == 0u) {
        unsigned m = g_m, m4 = (m + 3u) >> 2;
        const uint4* s4 = (const uint4*)g_scratch;
        for (unsigned i = blockIdx.x * 256 + tid; i < m4; i += stride) {
            uint4 u = s4[i];
            unsigned b = i * 4;
            if (b + 0 < m) atomicAdd(&sh[u.x >> 20], 1u);
            if (b + 1 < m) atomicAdd(&sh[u.y >> 20], 1u);
            if (b + 2 < m) atomicAdd(&sh[u.z >> 20], 1u);
            if (b + 3 < m) atomicAdd(&sh[u.w >> 20], 1u);
        }
    } else {
        for (unsigned i = blockIdx.x * 256 + tid; i < (unsigned)n4; i += stride) {
            float4 v = x[i];
            atomicAdd(&sh[fkey(v.x) >> 20], 1u);
            atomicAdd(&sh[fkey(v.y) >> 20], 1u);
            atomicAdd(&sh[fkey(v.z) >> 20], 1u);
            atomicAdd(&sh[fkey(v.w) >> 20], 1u);
        }
        if (blockIdx.x == 0 && tid == 0) {
            const float* xf = (const float*)x;
            for (int j = n4 * 4; j < n; j++) atomicAdd(&sh[fkey(xf[j]) >> 20], 1u);
        }
    }
    __syncthreads();
    for (int i = tid; i < NB_A; i += 256)
        if (sh[i]) atomicAdd(&g_hA[i], sh[i]);

    __threadfence();
    if (tid == 0) s_last = (atomicAdd(&g_tk[1], 1u) == gridDim.x - 1u) ? 1u : 0u;
    __syncthreads();
    if (!s_last) return;
    __threadfence();

    unsigned c[16], s = 0;
    #pragma unroll
    for (int j = 0; j < 16; j++) { c[j] = g_hA[tid * 16 + j]; s += c[j]; }
    ps[tid] = s;
    __syncthreads();
    for (int off = 1; off < 256; off <<= 1) {
        unsigned v = (tid >= off) ? ps[tid - off] : 0u;
        __syncthreads();
        ps[tid] += v;
        __syncthreads();
    }
    unsigned k = g_rank, incl = ps[tid], excl = incl - s;
    if (k >= excl && k < incl) {
        unsigned r = k - excl;
        #pragma unroll
        for (int j = 0; j < 16; j++) {
            if (r < c[j]) { g_b1 = tid * 16 + j; g_k2 = r; break; }
            r -= c[j];
        }
    }
    #pragma unroll
    for (int j = 0; j < 16; j++) g_hA[tid * 16 + j] = 0;
    if (tid == 0) g_tk[1] = 0;
}

// ---------------- histB (bits 10..19) + fused select + self-zero -------------
__global__ __launch_bounds__(256) void histB_kernel(const float4* __restrict__ x,
                                                    int n4, int n) {
    __shared__ unsigned sh[NB_B];
    __shared__ unsigned ps[256];
    __shared__ unsigned s_last;
    int tid = threadIdx.x;
    for (int i = tid; i < NB_B; i += 256) sh[i] = 0;
    __syncthreads();

    unsigned b1 = g_b1;
    unsigned stride = gridDim.x * 256;
    if (g_use_fallback == 0u) {
        unsigned m = g_m, m4 = (m + 3u) >> 2;
        const uint4* s4 = (const uint4*)g_scratch;
        for (unsigned i = blockIdx.x * 256 + tid; i < m4; i += stride) {
            uint4 u = s4[i];
            unsigned b = i * 4;
            if (b + 0 < m && (u.x >> 20) == b1) atomicAdd(&sh[(u.x >> 10) & 1023u], 1u);
            if (b + 1 < m && (u.y >> 20) == b1) atomicAdd(&sh[(u.y >> 10) & 1023u], 1u);
            if (b + 2 < m && (u.z >> 20) == b1) atomicAdd(&sh[(u.z >> 10) & 1023u], 1u);
            if (b + 3 < m && (u.w >> 20) == b1) atomicAdd(&sh[(u.w >> 10) & 1023u], 1u);
        }
    } else {
        for (unsigned i = blockIdx.x * 256 + tid; i < (unsigned)n4; i += stride) {
            float4 v = x[i];
            unsigned u0 = fkey(v.x), u1 = fkey(v.y), u2 = fkey(v.z), u3 = fkey(v.w);
            if ((u0 >> 20) == b1) atomicAdd(&sh[(u0 >> 10) & 1023u], 1u);
            if ((u1 >> 20) == b1) atomicAdd(&sh[(u1 >> 10) & 1023u], 1u);
            if ((u2 >> 20) == b1) atomicAdd(&sh[(u2 >> 10) & 1023u], 1u);
            if ((u3 >> 20) == b1) atomicAdd(&sh[(u3 >> 10) & 1023u], 1u);
        }
        if (blockIdx.x == 0 && tid == 0) {
            const float* xf = (const float*)x;
            for (int j = n4 * 4; j < n; j++) {
                unsigned u = fkey(xf[j]);
                if ((u >> 20) == b1) atomicAdd(&sh[(u >> 10) & 1023u], 1u);
            }
        }
    }
    __syncthreads();
    for (int i = tid; i < NB_B; i += 256)
        if (sh[i]) atomicAdd(&g_hB[i], sh[i]);

    __threadfence();
    if (tid == 0) s_last = (atomicAdd(&g_tk[2], 1u) == gridDim.x - 1u) ? 1u : 0u;
    __syncthreads();
    if (!s_last) return;
    __threadfence();

    unsigned c[4], s = 0;
    #pragma unroll
    for (int j = 0; j < 4; j++) { c[j] = g_hB[tid * 4 + j]; s += c[j]; }
    ps[tid] = s;
    __syncthreads();
    for (int off = 1; off < 256; off <<= 1) {
        unsigned v = (tid >= off) ? ps[tid - off] : 0u;
        __syncthreads();
        ps[tid] += v;
        __syncthreads();
    }
    unsigned k = g_k2, incl = ps[tid], excl = incl - s;
    if (k >= excl && k < incl) {
        unsigned r = k - excl;
        #pragma unroll
        for (int j = 0; j < 4; j++) {
            if (r < c[j]) { g_b2 = tid * 4 + j; g_k3 = r; break; }
            r -= c[j];
        }
    }
    #pragma unroll
    for (int j = 0; j < 4; j++) g_hB[tid * 4 + j] = 0;
    if (tid == 0) g_tk[2] = 0;
}

// ---------------- histC (low 10 bits) + median + global self-reset -----------
__global__ __launch_bounds__(256) void histC_kernel(const float4* __restrict__ x,
                                                    int n4, int n) {
    __shared__ unsigned sh[NB_B];
    __shared__ unsigned ps[256];
    __shared__ unsigned s_last;
    int tid = threadIdx.x;
    for (int i = tid; i < NB_B; i += 256) sh[i] = 0;
    __syncthreads();

    unsigned hi = (g_b1 << 10) | g_b2;
    unsigned stride = gridDim.x * 256;
    if (g_use_fallback == 0u) {
        unsigned m = g_m, m4 = (m + 3u) >> 2;
        const uint4* s4 = (const uint4*)g_scratch;
        for (unsigned i = blockIdx.x * 256 + tid; i < m4; i += stride) {
            uint4 u = s4[i];
            unsigned b = i * 4;
            if (b + 0 < m && (u.x >> 10) == hi) atomicAdd(&sh[u.x & 1023u], 1u);
            if (b + 1 < m && (u.y >> 10) == hi) atomicAdd(&sh[u.y & 1023u], 1u);
            if (b + 2 < m && (u.z >> 10) == hi) atomicAdd(&sh[u.z & 1023u], 1u);
            if (b + 3 < m && (u.w >> 10) == hi) atomicAdd(&sh[u.w & 1023u], 1u);
        }
    } else {
        for (unsigned i = blockIdx.x * 256 + tid; i < (unsigned)n4; i += stride) {
            float4 v = x[i];
            unsigned u0 = fkey(v.x), u1 = fkey(v.y), u2 = fkey(v.z), u3 = fkey(v.w);
            if ((u0 >> 10) == hi) atomicAdd(&sh[u0 & 1023u], 1u);
            if ((u1 >> 10) == hi) atomicAdd(&sh[u1 & 1023u], 1u);
            if ((u2 >> 10) == hi) atomicAdd(&sh[u2 & 1023u], 1u);
            if ((u3 >> 10) == hi) atomicAdd(&sh[u3 & 1023u], 1u);
        }
        if (blockIdx.x == 0 && tid == 0) {
            const float* xf = (const float*)x;
            for (int j = n4 * 4; j < n; j++) {
                unsigned u = fkey(xf[j]);
                if ((u >> 10) == hi) atomicAdd(&sh[u & 1023u], 1u);
            }
        }
    }
    __syncthreads();
    for (int i = tid; i < NB_B; i += 256)
        if (sh[i]) atomicAdd(&g_hC[i], sh[i]);

    __threadfence();
    if (tid == 0) s_last = (atomicAdd(&g_tk[3], 1u) == gridDim.x - 1u) ? 1u : 0u;
    __syncthreads();
    if (!s_last) return;
    __threadfence();

    unsigned c[4], s = 0;
    #pragma unroll
    for (int j = 0; j < 4; j++) { c[j] = g_hC[tid * 4 + j]; s += c[j]; }
    ps[tid] = s;
    __syncthreads();
    for (int off = 1; off < 256; off <<= 1) {
        unsigned v = (tid >= off) ? ps[tid - off] : 0u;
        __syncthreads();
        ps[tid] += v;
        __syncthreads();
    }
    unsigned k = g_k3, incl = ps[tid], excl = incl - s;
    if (k >= excl && k < incl) {
        unsigned r = k - excl;
        #pragma unroll
        for (int j = 0; j < 4; j++) {
            if (r < c[j]) {
                unsigned key  = ((g_b1 << 20) | (g_b2 << 10)) | (unsigned)(tid * 4 + j);
                unsigned bits = (key & 0x80000000u) ? (key ^ 0x80000000u) : ~key;
                g_median = __uint_as_float(bits);
                break;
            }
            r -= c[j];
        }
    }
    #pragma unroll
    for (int j = 0; j < 4; j++) g_hC[tid * 4 + j] = 0;
    if (tid == 0) { g_below = 0; g_m = 0; g_overflow = 0; g_tk[3] = 0; }
}

// ---------------- fused threshold + 7x7 maxpool + NMS (vectorized) -----------
#define IMG_W  2048
#define IMG_H  2048
#define IMG_W4 512
#define TW  128
#define TH  32
#define SWP 136     // padded tile width in floats (34 float4: cols -4..131)
#define SHH 38      // 32 + 2*3 halo rows

__global__ __launch_bounds__(256) void nms_kernel(const float4* __restrict__ x4,
                                                  float4* __restrict__ o4) {
    __shared__ float sthr[SHH][SWP];
    __shared__ float shm[SHH][TW];
    const float med = g_median;
    int tid = threadIdx.x;
    int bx = blockIdx.x, by = blockIdx.y;
    const float4* img  = x4 + (size_t)blockIdx.z * IMG_W4 * IMG_H;
    float4*       oimg = o4 + (size_t)blockIdx.z * IMG_W4 * IMG_H;
    int gx4_0 = bx * (TW / 4) - 1;
    int gy0   = by * TH - 3;

    for (int idx = tid; idx < SHH * 34; idx += 256) {
        int r = idx / 34, q = idx - r * 34;
        int gy = gy0 + r, gx4 = gx4_0 + q;
        float4 v = make_float4(-CUDART_INF_F, -CUDART_INF_F, -CUDART_INF_F, -CUDART_INF_F);
        if (gy >= 0 && gy < IMG_H && gx4 >= 0 && gx4 < IMG_W4) {
            float4 t = img[(size_t)gy * IMG_W4 + gx4];
            v.x = (t.x > med) ? t.x : 0.0f;
            v.y = (t.y > med) ? t.y : 0.0f;
            v.z = (t.z > med) ? t.z : 0.0f;
            v.w = (t.w > med) ? t.w : 0.0f;
        }
        *(float4*)&sthr[r][q * 4] = v;
    }
    __syncthreads();

    for (int idx = tid; idx < SHH * 32; idx += 256) {
        int r = idx >> 5, t = idx & 31;
        float4 a = *(const float4*)&sthr[r][t * 4];
        float4 b = *(const float4*)&sthr[r][t * 4 + 4];
        float4 cc = *(const float4*)&sthr[r][t * 4 + 8];
        float m45 = fmaxf(b.x, b.y), m67 = fmaxf(b.z, b.w);
        float m4567 = fmaxf(m45, m67);
        float m23 = fmaxf(a.z, a.w);
        float m89 = fmaxf(cc.x, cc.y);
        float m0 = fmaxf(fmaxf(a.y, m23), m4567);
        float m1 = fmaxf(fmaxf(m23, m4567), cc.x);
        float m2 = fmaxf(fmaxf(a.w, m4567), m89);
        float m3 = fmaxf(fmaxf(m4567, m89), cc.z);
        *(float4*)&shm[r][t * 4] = make_float4(m0, m1, m2, m3);
    }
    __syncthreads();

    for (int idx = tid; idx < TH * 32; idx += 256) {
        int r = idx >> 5, t = idx & 31;
        float4 m = *(const float4*)&shm[r][t * 4];
        #pragma unroll
        for (int o = 1; o < 7; o++) {
            float4 w = *(const float4*)&shm[r + o][t * 4];
            m.x = fmaxf(m.x, w.x);
            m.y = fmaxf(m.y, w.y);
            m.z = fmaxf(m.z, w.z);
            m.w = fmaxf(m.w, w.w);
        }
        float4 cen = *(const float4*)&sthr[r + 3][t * 4 + 4];
        float4 outv;
        outv.x = (cen.x == m.x) ? cen.x : 0.0f;
        outv.y = (cen.y == m.y) ? cen.y : 0.0f;
        outv.z = (cen.z == m.z) ? cen.z : 0.0f;
        outv.w = (cen.w == m.w) ? cen.w : 0.0f;
        int gy = by * TH + r;
        oimg[(size_t)gy * IMG_W4 + bx * 32 + t] = outv;
    }
}

// ---------------- launch -----------------------------------------------------
extern "C" void kernel_launch(void* const* d_in, const int* in_sizes, int n_in,
                              void* d_out, int out_size) {
    const float* x = (const float*)d_in[0];
    float* out = (float*)d_out;
    int n = in_sizes[0];
    int n4 = n >> 2;
    unsigned k = (unsigned)((n - 1) / 2);

    int dev = 0, sms = 148;
    cudaGetDevice(&dev);
    cudaDeviceGetAttribute(&sms, cudaDevAttrMultiProcessorCount, dev);

    pass1_kernel<<<sms * 4, 512>>>((const float4*)x, n4, n, k);
    histA_kernel<<<128, 256>>>((const float4*)x, n4, n);
    histB_kernel<<<128, 256>>>((const float4*)x, n4, n);
    histC_kernel<<<128, 256>>>((const float4*)x, n4, n);
    nms_kernel<<<dim3(IMG_W / TW, IMG_H / TH, 8), 256>>>((const float4*)x, (float4*)out);
}

// round 17
// speedup vs baseline: 1.3451x; 1.2700x over previous
#include <cuda_runtime.h>
#include <math_constants.h>

// ---------------- configuration ---------------------------------------------
#define KEY_LO 0x42FFFFFFu   // fkey(-0.03125f)
#define KEY_HI 0xBD000000u   // fkey(+0.03125f)
#define GCAP   (1u << 22)    // 4M-key scratch (16 MB)
#define BCAP   8192          // per-block smem append buffer
#define NB_A   4096
#define NB_B   1024

// ---------------- device state (allocation-free, self-restoring) -------------
__device__ __align__(16) unsigned g_scratch[GCAP];
__device__ unsigned g_hA[NB_A];
__device__ unsigned g_hB[NB_B];
__device__ unsigned g_hC[NB_B];
__device__ unsigned g_below, g_m, g_overflow, g_use_fallback, g_rank;
__device__ unsigned g_b1, g_k2, g_b2, g_k3;
__device__ unsigned g_tk[4];
__device__ float    g_median;

// monotonic key: order-preserving float -> uint
__device__ __forceinline__ unsigned fkey(float f) {
    unsigned b = __float_as_uint(f);
    unsigned mask = (unsigned)((int)b >> 31) | 0x80000000u;
    return b ^ mask;
}

// ---------------- pass 1: ballot compaction (R3-proven) + fused decide -------
__global__ __launch_bounds__(512) void pass1_kernel(const float4* __restrict__ x,
                                                    int n4, int n, unsigned k) {
    __shared__ unsigned buf[BCAP];
    __shared__ unsigned s_cnt, s_base, s_last;
    int tid = threadIdx.x, lane = tid & 31;
    if (tid == 0) s_cnt = 0;
    __syncthreads();

    unsigned below = 0;
    int stride = gridDim.x * blockDim.x;
    int i = blockIdx.x * blockDim.x + tid;
    const float4 FILL = make_float4(CUDART_INF_F, CUDART_INF_F, CUDART_INF_F, CUDART_INF_F);
    const unsigned lanemask = (1u << lane) - 1u;

    for (;;) {
        bool r0 = i < n4;
        if (!__any_sync(0xffffffffu, r0)) break;
        bool r1 = (i + stride) < n4;
        float4 v0 = FILL, v1 = FILL;          // +inf key: not below, not in window
        if (r0) v0 = x[i];
        if (r1) v1 = x[i + stride];

        unsigned kk[8];
        kk[0] = fkey(v0.x); kk[1] = fkey(v0.y); kk[2] = fkey(v0.z); kk[3] = fkey(v0.w);
        kk[4] = fkey(v1.x); kk[5] = fkey(v1.y); kk[6] = fkey(v1.z); kk[7] = fkey(v1.w);

        unsigned msk[8], tot = 0;
        #pragma unroll
        for (int j = 0; j < 8; j++) {
            below += (kk[j] < KEY_LO) ? 1u : 0u;
            bool w = (kk[j] - KEY_LO) < (KEY_HI - KEY_LO);
            msk[j] = __ballot_sync(0xffffffffu, w);
            tot += __popc(msk[j]);
        }
        if (tot) {
            unsigned base = 0;
            if (lane == 0) base = atomicAdd(&s_cnt, tot);   // ONE smem atomic / warp-iter
            base = __shfl_sync(0xffffffffu, base, 0);
            #pragma unroll
            for (int j = 0; j < 8; j++) {
                if (msk[j] & (1u << lane)) {
                    unsigned p = base + __popc(msk[j] & lanemask);
                    if (p < BCAP) buf[p] = kk[j];
                    else g_overflow = 1u;
                }
                base += __popc(msk[j]);
            }
        }
        i += 2 * stride;
    }

    // scalar tail (n not multiple of 4)
    if (blockIdx.x == 0 && tid == 0) {
        const float* xf = (const float*)x;
        for (int j = n4 * 4; j < n; j++) {
            unsigned key = fkey(xf[j]);
            if (key < KEY_LO) below++;
            else if ((key - KEY_LO) < (KEY_HI - KEY_LO)) {
                unsigned p = atomicAdd(&s_cnt, 1u);
                if (p < BCAP) buf[p] = key;
                else g_overflow = 1u;
            }
        }
    }

    #pragma unroll
    for (int o = 16; o; o >>= 1) below += __shfl_down_sync(0xffffffffu, below, o);
    if (lane == 0 && below) atomicAdd(&g_below, below);

    __syncthreads();
    if (tid == 0) {
        unsigned c = s_cnt;
        if (c > BCAP) { c = BCAP; g_overflow = 1u; }
        s_cnt = c;
        s_base = atomicAdd(&g_m, c);
    }
    __syncthreads();
    unsigned cnt = s_cnt, gbase = s_base;
    for (unsigned j = tid; j < cnt; j += 512) {
        if (gbase + j < GCAP) g_scratch[gbase + j] = buf[j];
        else g_overflow = 1u;
    }

    // last block decides speculation hit vs fallback (proven ticket pattern)
    __threadfence();
    if (tid == 0) s_last = (atomicAdd(&g_tk[0], 1u) == gridDim.x - 1u) ? 1u : 0u;
    __syncthreads();
    if (s_last && tid == 0) {
        __threadfence();
        unsigned b = g_below, m = g_m;
        bool hit = (g_overflow == 0u) && (k >= b) && ((k - b) < m) && (m <= GCAP);
        g_use_fallback = hit ? 0u : 1u;
        g_rank = hit ? (k - b) : k;
        g_tk[0] = 0;
    }
}

// ---------------- histA (top 12 bits) + fused select + self-zero -------------
__global__ __launch_bounds__(256) void histA_kernel(const float4* __restrict__ x,
                                                    int n4, int n) {
    __shared__ unsigned sh[NB_A];
    __shared__ unsigned ps[256];
    __shared__ unsigned s_last;
    int tid = threadIdx.x;
    for (int i = tid; i < NB_A; i += 256) sh[i] = 0;
    __syncthreads();

    unsigned stride = gridDim.x * 256;
    if (g_use_fallback == 0u) {
        unsigned m = g_m, m4 = (m + 3u) >> 2;
        const uint4* s4 = (const uint4*)g_scratch;
        for (unsigned i = blockIdx.x * 256 + tid; i < m4; i += stride) {
            uint4 u = s4[i];
            unsigned b = i * 4;
            if (b + 0 < m) atomicAdd(&sh[u.x >> 20], 1u);
            if (b + 1 < m) atomicAdd(&sh[u.y >> 20], 1u);
            if (b + 2 < m) atomicAdd(&sh[u.z >> 20], 1u);
            if (b + 3 < m) atomicAdd(&sh[u.w >> 20], 1u);
        }
    } else {
        for (unsigned i = blockIdx.x * 256 + tid; i < (unsigned)n4; i += stride) {
            float4 v = x[i];
            atomicAdd(&sh[fkey(v.x) >> 20], 1u);
            atomicAdd(&sh[fkey(v.y) >> 20], 1u);
            atomicAdd(&sh[fkey(v.z) >> 20], 1u);
            atomicAdd(&sh[fkey(v.w) >> 20], 1u);
        }
        if (blockIdx.x == 0 && tid == 0) {
            const float* xf = (const float*)x;
            for (int j = n4 * 4; j < n; j++) atomicAdd(&sh[fkey(xf[j]) >> 20], 1u);
        }
    }
    __syncthreads();
    for (int i = tid; i < NB_A; i += 256)
        if (sh[i]) atomicAdd(&g_hA[i], sh[i]);

    __threadfence();
    if (tid == 0) s_last = (atomicAdd(&g_tk[1], 1u) == gridDim.x - 1u) ? 1u : 0u;
    __syncthreads();
    if (!s_last) return;
    __threadfence();

    unsigned c[16], s = 0;
    #pragma unroll
    for (int j = 0; j < 16; j++) { c[j] = g_hA[tid * 16 + j]; s += c[j]; }
    ps[tid] = s;
    __syncthreads();
    for (int off = 1; off < 256; off <<= 1) {
        unsigned v = (tid >= off) ? ps[tid - off] : 0u;
        __syncthreads();
        ps[tid] += v;
        __syncthreads();
    }
    unsigned k = g_rank, incl = ps[tid], excl = incl - s;
    if (k >= excl && k < incl) {
        unsigned r = k - excl;
        #pragma unroll
        for (int j = 0; j < 16; j++) {
            if (r < c[j]) { g_b1 = tid * 16 + j; g_k2 = r; break; }
            r -= c[j];
        }
    }
    #pragma unroll
    for (int j = 0; j < 16; j++) g_hA[tid * 16 + j] = 0;
    if (tid == 0) g_tk[1] = 0;
}

// ---------------- histB (bits 10..19) + fused select + self-zero -------------
__global__ __launch_bounds__(256) void histB_kernel(const float4* __restrict__ x,
                                                    int n4, int n) {
    __shared__ unsigned sh[NB_B];
    __shared__ unsigned ps[256];
    __shared__ unsigned s_last;
    int tid = threadIdx.x;
    for (int i = tid; i < NB_B; i += 256) sh[i] = 0;
    __syncthreads();

    unsigned b1 = g_b1;
    unsigned stride = gridDim.x * 256;
    if (g_use_fallback == 0u) {
        unsigned m = g_m, m4 = (m + 3u) >> 2;
        const uint4* s4 = (const uint4*)g_scratch;
        for (unsigned i = blockIdx.x * 256 + tid; i < m4; i += stride) {
            uint4 u = s4[i];
            unsigned b = i * 4;
            if (b + 0 < m && (u.x >> 20) == b1) atomicAdd(&sh[(u.x >> 10) & 1023u], 1u);
            if (b + 1 < m && (u.y >> 20) == b1) atomicAdd(&sh[(u.y >> 10) & 1023u], 1u);
            if (b + 2 < m && (u.z >> 20) == b1) atomicAdd(&sh[(u.z >> 10) & 1023u], 1u);
            if (b + 3 < m && (u.w >> 20) == b1) atomicAdd(&sh[(u.w >> 10) & 1023u], 1u);
        }
    } else {
        for (unsigned i = blockIdx.x * 256 + tid; i < (unsigned)n4; i += stride) {
            float4 v = x[i];
            unsigned u0 = fkey(v.x), u1 = fkey(v.y), u2 = fkey(v.z), u3 = fkey(v.w);
            if ((u0 >> 20) == b1) atomicAdd(&sh[(u0 >> 10) & 1023u], 1u);
            if ((u1 >> 20) == b1) atomicAdd(&sh[(u1 >> 10) & 1023u], 1u);
            if ((u2 >> 20) == b1) atomicAdd(&sh[(u2 >> 10) & 1023u], 1u);
            if ((u3 >> 20) == b1) atomicAdd(&sh[(u3 >> 10) & 1023u], 1u);
        }
        if (blockIdx.x == 0 && tid == 0) {
            const float* xf = (const float*)x;
            for (int j = n4 * 4; j < n; j++) {
                unsigned u = fkey(xf[j]);
                if ((u >> 20) == b1) atomicAdd(&sh[(u >> 10) & 1023u], 1u);
            }
        }
    }
    __syncthreads();
    for (int i = tid; i < NB_B; i += 256)
        if (sh[i]) atomicAdd(&g_hB[i], sh[i]);

    __threadfence();
    if (tid == 0) s_last = (atomicAdd(&g_tk[2], 1u) == gridDim.x - 1u) ? 1u : 0u;
    __syncthreads();
    if (!s_last) return;
    __threadfence();

    unsigned c[4], s = 0;
    #pragma unroll
    for (int j = 0; j < 4; j++) { c[j] = g_hB[tid * 4 + j]; s += c[j]; }
    ps[tid] = s;
    __syncthreads();
    for (int off = 1; off < 256; off <<= 1) {
        unsigned v = (tid >= off) ? ps[tid - off] : 0u;
        __syncthreads();
        ps[tid] += v;
        __syncthreads();
    }
    unsigned k = g_k2, incl = ps[tid], excl = incl - s;
    if (k >= excl && k < incl) {
        unsigned r = k - excl;
        #pragma unroll
        for (int j = 0; j < 4; j++) {
            if (r < c[j]) { g_b2 = tid * 4 + j; g_k3 = r; break; }
            r -= c[j];
        }
    }
    #pragma unroll
    for (int j = 0; j < 4; j++) g_hB[tid * 4 + j] = 0;
    if (tid == 0) g_tk[2] = 0;
}

// ---------------- histC (low 10 bits) + median + global self-reset -----------
__global__ __launch_bounds__(256) void histC_kernel(const float4* __restrict__ x,
                                                    int n4, int n) {
    __shared__ unsigned sh[NB_B];
    __shared__ unsigned ps[256];
    __shared__ unsigned s_last;
    int tid = threadIdx.x;
    for (int i = tid; i < NB_B; i += 256) sh[i] = 0;
    __syncthreads();

    unsigned hi = (g_b1 << 10) | g_b2;
    unsigned stride = gridDim.x * 256;
    if (g_use_fallback == 0u) {
        unsigned m = g_m, m4 = (m + 3u) >> 2;
        const uint4* s4 = (const uint4*)g_scratch;
        for (unsigned i = blockIdx.x * 256 + tid; i < m4; i += stride) {
            uint4 u = s4[i];
            unsigned b = i * 4;
            if (b + 0 < m && (u.x >> 10) == hi) atomicAdd(&sh[u.x & 1023u], 1u);
            if (b + 1 < m && (u.y >> 10) == hi) atomicAdd(&sh[u.y & 1023u], 1u);
            if (b + 2 < m && (u.z >> 10) == hi) atomicAdd(&sh[u.z & 1023u], 1u);
            if (b + 3 < m && (u.w >> 10) == hi) atomicAdd(&sh[u.w & 1023u], 1u);
        }
    } else {
        for (unsigned i = blockIdx.x * 256 + tid; i < (unsigned)n4; i += stride) {
            float4 v = x[i];
            unsigned u0 = fkey(v.x), u1 = fkey(v.y), u2 = fkey(v.z), u3 = fkey(v.w);
            if ((u0 >> 10) == hi) atomicAdd(&sh[u0 & 1023u], 1u);
            if ((u1 >> 10) == hi) atomicAdd(&sh[u1 & 1023u], 1u);
            if ((u2 >> 10) == hi) atomicAdd(&sh[u2 & 1023u], 1u);
            if ((u3 >> 10) == hi) atomicAdd(&sh[u3 & 1023u], 1u);
        }
        if (blockIdx.x == 0 && tid == 0) {
            const float* xf = (const float*)x;
            for (int j = n4 * 4; j < n; j++) {
                unsigned u = fkey(xf[j]);
                if ((u >> 10) == hi) atomicAdd(&sh[u & 1023u], 1u);
            }
        }
    }
    __syncthreads();
    for (int i = tid; i < NB_B; i += 256)
        if (sh[i]) atomicAdd(&g_hC[i], sh[i]);

    __threadfence();
    if (tid == 0) s_last = (atomicAdd(&g_tk[3], 1u) == gridDim.x - 1u) ? 1u : 0u;
    __syncthreads();
    if (!s_last) return;
    __threadfence();

    unsigned c[4], s = 0;
    #pragma unroll
    for (int j = 0; j < 4; j++) { c[j] = g_hC[tid * 4 + j]; s += c[j]; }
    ps[tid] = s;
    __syncthreads();
    for (int off = 1; off < 256; off <<= 1) {
        unsigned v = (tid >= off) ? ps[tid - off] : 0u;
        __syncthreads();
        ps[tid] += v;
        __syncthreads();
    }
    unsigned k = g_k3, incl = ps[tid], excl = incl - s;
    if (k >= excl && k < incl) {
        unsigned r = k - excl;
        #pragma unroll
        for (int j = 0; j < 4; j++) {
            if (r < c[j]) {
                unsigned key  = ((g_b1 << 20) | (g_b2 << 10)) | (unsigned)(tid * 4 + j);
                unsigned bits = (key & 0x80000000u) ? (key ^ 0x80000000u) : ~key;
                g_median = __uint_as_float(bits);
                break;
            }
            r -= c[j];
        }
    }
    #pragma unroll
    for (int j = 0; j < 4; j++) g_hC[tid * 4 + j] = 0;
    if (tid == 0) { g_below = 0; g_m = 0; g_overflow = 0; g_tk[3] = 0; }
}

// ---------------- fused threshold + 7x7 maxpool + NMS (R3-proven scalar) -----
#define TW 128
#define TH 32
#define HALO 3
#define SW (TW + 2 * HALO)   // 134
#define SHR (TH + 2 * HALO)  // 38
#define IMG_W 2048
#define IMG_H 2048

__global__ __launch_bounds__(256) void nms_kernel(const float* __restrict__ x,
                                                  float* __restrict__ out) {
    __shared__ float sthr[SHR][SW];
    __shared__ float shm[SHR][TW];
    const float med = g_median;

    int tx = threadIdx.x & 31;
    int ty = threadIdx.x >> 5;
    int x0 = blockIdx.x * TW - HALO;
    int y0 = blockIdx.y * TH - HALO;
    const float* img = x + (size_t)blockIdx.z * IMG_W * IMG_H;
    float* oimg = out + (size_t)blockIdx.z * IMG_W * IMG_H;

    #pragma unroll
    for (int i = 0; i < 5; i++) {
        int r = ty + 8 * i;
        if (r < SHR) {
            int gy = y0 + r;
            bool rowok = (gy >= 0 && gy < IMG_H);
            #pragma unroll
            for (int j = 0; j < 5; j++) {
                int c = tx + 32 * j;
                if (c < SW) {
                    int gx = x0 + c;
                    float v = -CUDART_INF_F;
                    if (rowok && gx >= 0 && gx < IMG_W) {
                        float t = img[(size_t)gy * IMG_W + gx];
                        v = (t > med) ? t : 0.0f;
                    }
                    sthr[r][c] = v;
                }
            }
        }
    }
    __syncthreads();

    #pragma unroll
    for (int i = 0; i < 5; i++) {
        int r = ty + 8 * i;
        if (r < SHR) {
            #pragma unroll
            for (int j = 0; j < 4; j++) {
                int c = tx + 32 * j;
                float m = sthr[r][c];
                #pragma unroll
                for (int o = 1; o < 7; o++) m = fmaxf(m, sthr[r][c + o]);
                shm[r][c] = m;
            }
        }
    }
    __syncthreads();

    #pragma unroll
    for (int i = 0; i < 4; i++) {
        int r = ty + 8 * i;
        int gy = blockIdx.y * TH + r;
        #pragma unroll
        for (int j = 0; j < 4; j++) {
            int c = tx + 32 * j;
            float m = shm[r][c];
            #pragma unroll
            for (int o = 1; o < 7; o++) m = fmaxf(m, shm[r + o][c]);
            float v = sthr[r + HALO][c + HALO];
            int gx = blockIdx.x * TW + c;
            oimg[(size_t)gy * IMG_W + gx] = (v == m) ? v : 0.0f;
        }
    }
}

// ---------------- launch -----------------------------------------------------
extern "C" void kernel_launch(void* const* d_in, const int* in_sizes, int n_in,
                              void* d_out, int out_size) {
    const float* x = (const float*)d_in[0];
    float* out = (float*)d_out;
    int n = in_sizes[0];
    int n4 = n >> 2;
    unsigned k = (unsigned)((n - 1) / 2);

    int dev = 0, sms = 148;
    cudaGetDevice(&dev);
    cudaDeviceGetAttribute(&sms, cudaDevAttrMultiProcessorCount, dev);

    pass1_kernel<<<sms * 4, 512>>>((const float4*)x, n4, n, k);
    histA_kernel<<<128, 256>>>((const float4*)x, n4, n);
    histB_kernel<<<128, 256>>>((const float4*)x, n4, n);
    histC_kernel<<<128, 256>>>((const float4*)x, n4, n);
    nms_kernel<<<dim3(IMG_W / TW, IMG_H / TH, 8), 256>>>(x, out);
}